// round 6
// baseline (speedup 1.0000x reference)
#include <cuda_runtime.h>
#include <cstdint>

#define NN 100000
#define NE 1600000
#define HD 64
#define NL 3
#define NGR 1000
#define MT 128
#define MBLOCKS ((NN + MT - 1) / MT)   // 782

// ---------------- device scratch (allocation-free) ----------------
__device__ float g_h[(size_t)NN * HD];
__device__ float g_agg[(size_t)NN * HD];
__device__ float g_y[(size_t)NN * HD];
__device__ float g_hcat[(size_t)NN * HD * NL];
__device__ float g_gate[NN];
__device__ float g_e[NN];
__device__ float g_scale[HD];
__device__ float g_shift[HD];
__device__ float g_bnsum[HD];
__device__ float g_bnsq[HD];
__device__ unsigned g_segmax[NGR];
__device__ float g_denom[NGR];

// ---------------- helpers ----------------
__device__ __forceinline__ unsigned encf(float f) {
    unsigned u = __float_as_uint(f);
    return (u & 0x80000000u) ? ~u : (u | 0x80000000u);
}
__device__ __forceinline__ float decf(unsigned e) {
    return __uint_as_float((e & 0x80000000u) ? (e & 0x7FFFFFFFu) : ~e);
}
__device__ __forceinline__ void red_add_v4(float* p, float4 v) {
    asm volatile("red.global.add.v4.f32 [%0], {%1,%2,%3,%4};"
                 :: "l"(p), "f"(v.x), "f"(v.y), "f"(v.z), "f"(v.w) : "memory");
}

// ---------------- zero kernels ----------------
__global__ void zero_agg_k() {
    int i = blockIdx.x * blockDim.x + threadIdx.x;
    if (i < NN * 16) ((float4*)g_agg)[i] = make_float4(0.f, 0.f, 0.f, 0.f);
}
__global__ void zero_misc_k() {
    int i = blockIdx.x * blockDim.x + threadIdx.x;
    if (i < NGR) { g_denom[i] = 0.f; g_segmax[i] = 0u; }
    if (i < HD) { g_bnsum[i] = 0.f; g_bnsq[i] = 0.f; }
}
__global__ void zero_buf_k(float* p, int n4) {
    int i = blockIdx.x * blockDim.x + threadIdx.x;
    if (i < n4) ((float4*)p)[i] = make_float4(0.f, 0.f, 0.f, 0.f);
}

// ---------------- edge scatter: agg[dst] += h[src] ----------------
__global__ void scatter_k(const float* __restrict__ hx, const int* __restrict__ ei, int l) {
    const float* __restrict__ h = (l == 0) ? hx : g_h;
    int gid = blockIdx.x * blockDim.x + threadIdx.x;
    if (gid >= NE * 16) return;
    int e = gid >> 4;
    int j = (gid & 15) << 2;
    int src = ei[e];
    int dst = ei[NE + e];
    float4 v = *(const float4*)(h + (size_t)src * HD + j);
    red_add_v4(g_agg + (size_t)dst * HD + j, v);
}

// ---------------- GEMM 64x64 with fused input transform + BN stats ----------------
// MODE 0: z = (1+eps[l])*h + agg   (h = x for l==0 else g_h), y = z@W + b  -> g_y
// MODE 1: z = relu(g_y*scale + shift), y = z@W + b                         -> g_y (in-place)
// Both accumulate column sum / sumsq of y into g_bnsum / g_bnsq.
template <int MODE>
__global__ __launch_bounds__(256) void gemm_bn_k(const float* __restrict__ Ax,
                                                 const float* __restrict__ W,
                                                 const float* __restrict__ bias,
                                                 const float* __restrict__ epsv, int l) {
    __shared__ float As[HD * MT];   // transposed: As[k][m]
    __shared__ float Bs[HD * HD];   // Bs[k][n]
    const int t = threadIdx.x;
    const int m0 = blockIdx.x * MT;

    for (int i = t; i < HD * HD; i += 256) Bs[i] = W[i];
    {
        const float* __restrict__ A = (MODE == 0) ? ((l == 0) ? Ax : g_h) : g_y;
        float ep = (MODE == 0) ? (1.0f + epsv[l]) : 0.f;
        int r = t >> 1;
        int k0 = (t & 1) * 32;
        int m = m0 + r;
#pragma unroll
        for (int kk = 0; kk < 32; kk += 4) {
            int k = k0 + kk;
            float4 v;
            if (m < NN) {
                float4 a = *(const float4*)(A + (size_t)m * HD + k);
                if (MODE == 0) {
                    float4 b = *(const float4*)(g_agg + (size_t)m * HD + k);
                    v = make_float4(fmaf(ep, a.x, b.x), fmaf(ep, a.y, b.y),
                                    fmaf(ep, a.z, b.z), fmaf(ep, a.w, b.w));
                } else {
                    float4 sc = *(const float4*)(g_scale + k);
                    float4 sh = *(const float4*)(g_shift + k);
                    v = make_float4(fmaxf(fmaf(a.x, sc.x, sh.x), 0.f),
                                    fmaxf(fmaf(a.y, sc.y, sh.y), 0.f),
                                    fmaxf(fmaf(a.z, sc.z, sh.z), 0.f),
                                    fmaxf(fmaf(a.w, sc.w, sh.w), 0.f));
                }
            } else {
                v = make_float4(0.f, 0.f, 0.f, 0.f);
            }
            As[(k + 0) * MT + r] = v.x;
            As[(k + 1) * MT + r] = v.y;
            As[(k + 2) * MT + r] = v.z;
            As[(k + 3) * MT + r] = v.w;
        }
    }
    __syncthreads();

    const int lane = t & 31;
    const int mb = lane * 4;
    const int nb = (t >> 5) * 8;
    float acc[4][8];
#pragma unroll
    for (int r = 0; r < 4; r++)
#pragma unroll
        for (int c = 0; c < 8; c++) acc[r][c] = 0.f;

#pragma unroll
    for (int k = 0; k < HD; k++) {
        float4 a4 = *(const float4*)(As + k * MT + mb);
        float4 b0 = *(const float4*)(Bs + k * HD + nb);
        float4 b1 = *(const float4*)(Bs + k * HD + nb + 4);
        float av[4] = {a4.x, a4.y, a4.z, a4.w};
        float bv[8] = {b0.x, b0.y, b0.z, b0.w, b1.x, b1.y, b1.z, b1.w};
#pragma unroll
        for (int r = 0; r < 4; r++)
#pragma unroll
            for (int c = 0; c < 8; c++) acc[r][c] = fmaf(av[r], bv[c], acc[r][c]);
    }

    float bs[8];
#pragma unroll
    for (int c = 0; c < 8; c++) bs[c] = bias[nb + c];
#pragma unroll
    for (int r = 0; r < 4; r++)
#pragma unroll
        for (int c = 0; c < 8; c++) acc[r][c] += bs[c];

#pragma unroll
    for (int r = 0; r < 4; r++) {
        int m = m0 + mb + r;
        if (m < NN) {
            *(float4*)(g_y + (size_t)m * HD + nb) =
                make_float4(acc[r][0], acc[r][1], acc[r][2], acc[r][3]);
            *(float4*)(g_y + (size_t)m * HD + nb + 4) =
                make_float4(acc[r][4], acc[r][5], acc[r][6], acc[r][7]);
        }
    }

    // column stats: warp owns all 128 rows of its 8 columns
#pragma unroll
    for (int c = 0; c < 8; c++) {
        float ps = 0.f, pq = 0.f;
#pragma unroll
        for (int r = 0; r < 4; r++) {
            if (m0 + mb + r < NN) {
                float v = acc[r][c];
                ps += v;
                pq = fmaf(v, v, pq);
            }
        }
#pragma unroll
        for (int off = 16; off > 0; off >>= 1) {
            ps += __shfl_xor_sync(0xffffffffu, ps, off);
            pq += __shfl_xor_sync(0xffffffffu, pq, off);
        }
        if (lane == 0) {
            atomicAdd(&g_bnsum[nb + c], ps);
            atomicAdd(&g_bnsq[nb + c], pq);
        }
    }
}

// ---------------- BN finalize (per GEMM) ----------------
__global__ void statfin_k(const float* __restrict__ gamma, const float* __restrict__ beta) {
    int n = threadIdx.x;
    if (n < HD) {
        const float inv = 1.0f / (float)NN;
        float mean = g_bnsum[n] * inv;
        float var = g_bnsq[n] * inv - mean * mean;
        float s = gamma[n] * rsqrtf(var + 1e-5f);
        g_scale[n] = s;
        g_shift[n] = fmaf(-mean, s, beta[n]);
        g_bnsum[n] = 0.f;
        g_bnsq[n] = 0.f;
    }
}

// ---------------- layer finalize: h = relu(bn(y2)); also write hcat slab ----------------
__global__ void finalize_k(int l) {
    int gid = blockIdx.x * blockDim.x + threadIdx.x;
    if (gid >= NN * 16) return;
    int i = gid >> 4;
    int j = (gid & 15) << 2;
    float4 y = *(const float4*)(g_y + (size_t)i * HD + j);
    float4 sc = *(const float4*)(g_scale + j);
    float4 sh = *(const float4*)(g_shift + j);
    float4 v = make_float4(fmaxf(fmaf(y.x, sc.x, sh.x), 0.f),
                           fmaxf(fmaf(y.y, sc.y, sh.y), 0.f),
                           fmaxf(fmaf(y.z, sc.z, sh.z), 0.f),
                           fmaxf(fmaf(y.w, sc.w, sh.w), 0.f));
    *(float4*)(g_h + (size_t)i * HD + j) = v;
    *(float4*)(g_hcat + (size_t)i * (HD * NL) + l * HD + j) = v;
}

// ---------------- hh = relu(hcat @ lin1_W + lin1_b); gate + segment max ----------------
__global__ __launch_bounds__(256) void lin_gate_k(const float* __restrict__ lw,
                                                  const float* __restrict__ lb,
                                                  const float* __restrict__ gw,
                                                  const float* __restrict__ gb,
                                                  const int* __restrict__ batch,
                                                  float* __restrict__ hh) {
    __shared__ float As[HD * MT];
    __shared__ float Bs[HD * HD];
    const int t = threadIdx.x;
    const int m0 = blockIdx.x * MT;
    const int lane = t & 31;
    const int mb = lane * 4;
    const int nb = (t >> 5) * 8;

    float acc[4][8];
#pragma unroll
    for (int r = 0; r < 4; r++)
#pragma unroll
        for (int c = 0; c < 8; c++) acc[r][c] = 0.f;

    for (int kc = 0; kc < 3; kc++) {
        for (int i = t; i < HD * HD; i += 256) Bs[i] = lw[kc * HD * HD + i];
        {
            int r = t >> 1;
            int k0 = (t & 1) * 32;
            int m = m0 + r;
#pragma unroll
            for (int kk = 0; kk < 32; kk += 4) {
                int k = k0 + kk;
                float4 v = make_float4(0.f, 0.f, 0.f, 0.f);
                if (m < NN)
                    v = *(const float4*)(g_hcat + (size_t)m * (HD * NL) + kc * HD + k);
                As[(k + 0) * MT + r] = v.x;
                As[(k + 1) * MT + r] = v.y;
                As[(k + 2) * MT + r] = v.z;
                As[(k + 3) * MT + r] = v.w;
            }
        }
        __syncthreads();
#pragma unroll
        for (int k = 0; k < HD; k++) {
            float4 a4 = *(const float4*)(As + k * MT + mb);
            float4 b0 = *(const float4*)(Bs + k * HD + nb);
            float4 b1 = *(const float4*)(Bs + k * HD + nb + 4);
            float av[4] = {a4.x, a4.y, a4.z, a4.w};
            float bv[8] = {b0.x, b0.y, b0.z, b0.w, b1.x, b1.y, b1.z, b1.w};
#pragma unroll
            for (int r = 0; r < 4; r++)
#pragma unroll
                for (int c = 0; c < 8; c++) acc[r][c] = fmaf(av[r], bv[c], acc[r][c]);
        }
        __syncthreads();
    }

    float bs[8];
#pragma unroll
    for (int c = 0; c < 8; c++) bs[c] = lb[nb + c];
#pragma unroll
    for (int r = 0; r < 4; r++)
#pragma unroll
        for (int c = 0; c < 8; c++) acc[r][c] = fmaxf(acc[r][c] + bs[c], 0.f);

#pragma unroll
    for (int r = 0; r < 4; r++) {
        int m = m0 + mb + r;
        if (m < NN) {
            *(float4*)(hh + (size_t)m * HD + nb) =
                make_float4(acc[r][0], acc[r][1], acc[r][2], acc[r][3]);
            *(float4*)(hh + (size_t)m * HD + nb + 4) =
                make_float4(acc[r][4], acc[r][5], acc[r][6], acc[r][7]);
        }
    }

    // gate = hh @ gate_W + gate_b, per-row reduced across the 8 warps via smem (reuse Bs)
    float gwv[8];
#pragma unroll
    for (int c = 0; c < 8; c++) gwv[c] = gw[nb + c];
    float* sg = Bs;  // Bs no longer needed after final sync above
    if (t < MT) sg[t] = 0.f;
    __syncthreads();
#pragma unroll
    for (int r = 0; r < 4; r++) {
        if (m0 + mb + r < NN) {
            float gp = 0.f;
#pragma unroll
            for (int c = 0; c < 8; c++) gp = fmaf(acc[r][c], gwv[c], gp);
            atomicAdd(&sg[mb + r], gp);
        }
    }
    __syncthreads();
    if (t < MT) {
        int m = m0 + t;
        if (m < NN) {
            float gv = sg[t] + gb[0];
            g_gate[m] = gv;
            atomicMax(&g_segmax[batch[m]], encf(gv));
        }
    }
}

// ---------------- softmax exp + denom ----------------
__global__ void expsum_k(const int* __restrict__ batch) {
    int i = blockIdx.x * blockDim.x + threadIdx.x;
    if (i >= NN) return;
    int b = batch[i];
    float e = expf(g_gate[i] - decf(g_segmax[b]));
    g_e[i] = e;
    atomicAdd(&g_denom[b], e);
}

// ---------------- pooled[b] += hh[i] * alpha[i] ----------------
__global__ void pool_k(const int* __restrict__ batch, const float* __restrict__ hh,
                       float* __restrict__ pooled) {
    int gid = blockIdx.x * blockDim.x + threadIdx.x;
    if (gid >= NN * 16) return;
    int i = gid >> 4;
    int j = (gid & 15) << 2;
    int b = batch[i];
    float alpha = g_e[i] / g_denom[b];
    float4 v = *(const float4*)(hh + (size_t)i * HD + j);
    red_add_v4(pooled + (size_t)b * HD + j,
               make_float4(v.x * alpha, v.y * alpha, v.z * alpha, v.w * alpha));
}

// ---------------- launch ----------------
extern "C" void kernel_launch(void* const* d_in, const int* in_sizes, int n_in,
                              void* d_out, int out_size) {
    const float* x    = (const float*)d_in[0];
    const int*   ei   = (const int*)d_in[1];
    const int*   batch= (const int*)d_in[2];
    const float* eps  = (const float*)d_in[3];
    const float* W1   = (const float*)d_in[4];
    const float* b1   = (const float*)d_in[5];
    const float* g1   = (const float*)d_in[6];
    const float* be1  = (const float*)d_in[7];
    const float* W2   = (const float*)d_in[8];
    const float* b2   = (const float*)d_in[9];
    const float* g2   = (const float*)d_in[10];
    const float* be2  = (const float*)d_in[11];
    const float* lw   = (const float*)d_in[12];
    const float* lb   = (const float*)d_in[13];
    const float* gw   = (const float*)d_in[14];
    const float* gb   = (const float*)d_in[15];

    float* out    = (float*)d_out;
    float* hh     = out;
    float* pooled = out + (size_t)NN * HD;

    zero_misc_k<<<4, 256>>>();
    zero_buf_k<<<(NGR * HD / 4 + 255) / 256, 256>>>(pooled, NGR * HD / 4);

    for (int l = 0; l < NL; l++) {
        zero_agg_k<<<(NN * 16 + 255) / 256, 256>>>();
        scatter_k<<<(NE * 16 + 255) / 256, 256>>>(x, ei, l);
        gemm_bn_k<0><<<MBLOCKS, 256>>>(x, W1 + (size_t)l * HD * HD, b1 + l * HD, eps, l);
        statfin_k<<<1, 64>>>(g1 + l * HD, be1 + l * HD);
        gemm_bn_k<1><<<MBLOCKS, 256>>>(nullptr, W2 + (size_t)l * HD * HD, b2 + l * HD, eps, l);
        statfin_k<<<1, 64>>>(g2 + l * HD, be2 + l * HD);
        finalize_k<<<(NN * 16 + 255) / 256, 256>>>(l);
    }
    lin_gate_k<<<MBLOCKS, 256>>>(lw, lb, gw, gb, batch, hh);
    expsum_k<<<(NN + 255) / 256, 256>>>(batch);
    pool_k<<<(NN * 16 + 255) / 256, 256>>>(batch, hh, pooled);
}